// round 2
// baseline (speedup 1.0000x reference)
#include <cuda_runtime.h>

#define G   256
#define PX  258        // x dim: x+1 in [0,257]
#define PY  258        // y dim: y+1 in [0,257]
#define PZ  264        // z dim: z stored at z+4 (keeps float4 alignment), z+4 in [3,260]
#define NCELLS (G * G * G)

// Padded dense input grid (~70 MB) and dense output grid (64 MB).
// Static __device__ arrays are zero-initialized once; halo & unoccupied cells
// stay 0 forever (occupied cells are rewritten with identical values each
// replay -> deterministic).
__device__ float g_pad[PX * PY * PZ];
__device__ float g_outg[NCELLS];

__device__ __forceinline__ int pad_idx(int x, int y, int z) {
    return ((x + 1) * PY + (y + 1)) * PZ + (z + 4);
}

__global__ void scatter_kernel(const int* __restrict__ coords,
                               const float* __restrict__ feats,
                               int n) {
    int i = blockIdx.x * blockDim.x + threadIdx.x;
    if (i >= n) return;
    int x = coords[3 * i + 0];
    int y = coords[3 * i + 1];
    int z = coords[3 * i + 2];
    g_pad[pad_idx(x, y, z)] = feats[i];
}

// Dense 3x3x3 stencil over the whole grid.
// Block layout: 256 threads = 8 y-rows (one per warp) x 32 lanes (z groups of 4).
// Each block owns tile (x-chunk of 32) x (8 y) x (128 z) and marches along x.
// Loads are coalesced float4 + 2 scalars per z-line; x/y reuse is served by L1.
__global__ void __launch_bounds__(256) stencil_kernel(const float* __restrict__ W) {
    float w[27];
    #pragma unroll
    for (int k = 0; k < 27; k++) w[k] = __ldg(&W[k]);

    int tid  = threadIdx.x;
    int lane = tid & 31;       // z group
    int wy   = tid >> 5;       // y within tile (0..7)

    int b  = blockIdx.x;       // 512 blocks: [bx(8)][by(32)][bz(2)]
    int bz = b & 1;
    int by = (b >> 1) & 31;
    int bx = b >> 6;

    int y  = by * 8 + wy;
    int z  = bz * 128 + lane * 4;
    int x0 = bx * 32;

    for (int x = x0; x < x0 + 32; x++) {
        float a0 = 0.f, a1 = 0.f, a2 = 0.f, a3 = 0.f;
        #pragma unroll
        for (int dx = -1; dx <= 1; dx++) {
            #pragma unroll
            for (int dy = -1; dy <= 1; dy++) {
                const float* p = &g_pad[pad_idx(x + dx, y + dy, z)];
                float4 v  = *reinterpret_cast<const float4*>(p); // z..z+3
                float vm1 = p[-1];                               // z-1
                float vp4 = p[4];                                // z+4
                int kb = (dx + 1) * 9 + (dy + 1) * 3;
                float w0 = w[kb], w1 = w[kb + 1], w2 = w[kb + 2];
                a0 += w0 * vm1 + w1 * v.x + w2 * v.y;
                a1 += w0 * v.x + w1 * v.y + w2 * v.z;
                a2 += w0 * v.y + w1 * v.z + w2 * v.w;
                a3 += w0 * v.z + w1 * v.w + w2 * vp4;
            }
        }
        float4 r = make_float4(a0, a1, a2, a3);
        *reinterpret_cast<float4*>(&g_outg[(((x << 8) | y) << 8) | z]) = r;
    }
}

__global__ void gather_kernel(const int* __restrict__ coords,
                              float* __restrict__ out,
                              int n) {
    int i = blockIdx.x * blockDim.x + threadIdx.x;
    if (i >= n) return;
    int x = coords[3 * i + 0];
    int y = coords[3 * i + 1];
    int z = coords[3 * i + 2];
    out[i] = g_outg[(((x << 8) | y) << 8) | z];
}

extern "C" void kernel_launch(void* const* d_in, const int* in_sizes, int n_in,
                              void* d_out, int out_size) {
    const int*   coords = (const int*)d_in[0];   // (N,3) int32
    const float* feats  = (const float*)d_in[1]; // (N,1) float32
    const float* W      = (const float*)d_in[2]; // (27,1,1) float32
    float*       out    = (float*)d_out;         // (N,1) float32

    int n = in_sizes[1];

    const int T = 256;
    int blocks = (n + T - 1) / T;

    scatter_kernel<<<blocks, T>>>(coords, feats, n);
    stencil_kernel<<<512, 256>>>(W);
    gather_kernel<<<blocks, T>>>(coords, out, n);
}